// round 4
// baseline (speedup 1.0000x reference)
#include <cuda_runtime.h>
#include <math_constants.h>

// Problem dims (fixed by setup_inputs)
#define BB 32
#define TT 2048
#define DD 1024
#define SPLITS 64
#define TC (TT / SPLITS)      // 32 rows per block
#define RPI 4                 // rows per iteration
#define NTHR 256              // = DD/4 (one float4 lane per thread)

// Scratch (no cudaMalloc allowed)
__device__ float g_scores[BB * TT];
__device__ float g_part_m[BB * SPLITS];
__device__ float g_part_z[BB * SPLITS];
__device__ float g_part_c[(size_t)BB * SPLITS * DD];
__device__ unsigned int g_count[BB];   // zero-initialized; reset by consumer

// ---------------------------------------------------------------------------
// Single fused kernel. Each block = (split, batch): streams its T-chunk with
// online softmax, writes partials, then the LAST block per batch (atomic
// fan-in) combines partials and writes context + weights for that batch —
// overlapped with other batches' streaming.
// ---------------------------------------------------------------------------
__global__ __launch_bounds__(NTHR) void dpa_fused(const float* __restrict__ q,
                                                  const float* __restrict__ v,
                                                  float* __restrict__ out) {
    const int split = blockIdx.x;
    const int b     = blockIdx.y;
    const int tid   = threadIdx.x;
    const int lane  = tid & 31;
    const int warp  = tid >> 5;

    __shared__ float red[8][RPI];
    __shared__ float se[SPLITS];
    __shared__ float sM, sZ;
    __shared__ int   s_last;

    const float4 q4 = reinterpret_cast<const float4*>(q + (size_t)b * DD)[tid];

    float  m = -CUDART_INF_F;
    float  Z = 0.0f;
    float4 c = make_float4(0.f, 0.f, 0.f, 0.f);

    const int t0 = split * TC;
    const float4* vb = reinterpret_cast<const float4*>(v + (size_t)b * TT * DD) + tid;

    for (int it = 0; it < TC; it += RPI) {
        float4 vv[RPI];
        float  p[RPI];
#pragma unroll
        for (int r = 0; r < RPI; r++) {
            vv[r] = vb[(size_t)(t0 + it + r) * (DD / 4)];
            p[r]  = q4.x * vv[r].x + q4.y * vv[r].y + q4.z * vv[r].z + q4.w * vv[r].w;
        }
#pragma unroll
        for (int r = 0; r < RPI; r++) {
#pragma unroll
            for (int o = 16; o > 0; o >>= 1)
                p[r] += __shfl_xor_sync(0xffffffffu, p[r], o);
        }
        if (lane == 0) {
#pragma unroll
            for (int r = 0; r < RPI; r++) red[warp][r] = p[r];
        }
        __syncthreads();

        float s[RPI];
#pragma unroll
        for (int r = 0; r < RPI; r++) {
            float acc = 0.f;
#pragma unroll
            for (int w = 0; w < 8; w++) acc += red[w][r];
            s[r] = acc;
        }
        __syncthreads();  // before smem reuse next iter

        if (tid < RPI) g_scores[b * TT + t0 + it + tid] = s[tid];

        // Online softmax update (identical scalar math on all threads)
        float nm = m;
#pragma unroll
        for (int r = 0; r < RPI; r++) nm = fmaxf(nm, s[r]);
        const float f = __expf(m - nm);   // 0 on first iter (m = -inf)
        Z *= f;
        c.x *= f; c.y *= f; c.z *= f; c.w *= f;
#pragma unroll
        for (int r = 0; r < RPI; r++) {
            const float e = __expf(s[r] - nm);
            Z  += e;
            c.x += e * vv[r].x;
            c.y += e * vv[r].y;
            c.z += e * vv[r].z;
            c.w += e * vv[r].w;
        }
        m = nm;
    }

    // Publish per-split partials
    reinterpret_cast<float4*>(g_part_c + (size_t)(b * SPLITS + split) * DD)[tid] = c;
    if (tid == 0) {
        g_part_m[b * SPLITS + split] = m;
        g_part_z[b * SPLITS + split] = Z;
    }

    // Fan-in: last block for this batch does the combine.
    __syncthreads();
    if (tid == 0) {
        __threadfence();
        const unsigned int old = atomicAdd(&g_count[b], 1u);
        s_last = (old == SPLITS - 1);
    }
    __syncthreads();
    if (!s_last) return;
    __threadfence();  // acquire-ish: order our reads after the fan-in

    // ---- Combine stage (one block per batch, L2-resident data) ----
    // Global max M over 64 splits: warp 0, two elements per lane.
    if (warp == 0) {
        const float m0 = g_part_m[b * SPLITS + lane];
        const float m1 = g_part_m[b * SPLITS + lane + 32];
        float M = fmaxf(m0, m1);
#pragma unroll
        for (int o = 16; o > 0; o >>= 1)
            M = fmaxf(M, __shfl_xor_sync(0xffffffffu, M, o));
        const float e0 = __expf(m0 - M);
        const float e1 = __expf(m1 - M);
        se[lane]      = e0;
        se[lane + 32] = e1;
        float z = g_part_z[b * SPLITS + lane] * e0 +
                  g_part_z[b * SPLITS + lane + 32] * e1;
#pragma unroll
        for (int o = 16; o > 0; o >>= 1)
            z += __shfl_xor_sync(0xffffffffu, z, o);
        if (lane == 0) { sM = g_part_m[b * SPLITS] * 0.f + M; sZ = z; }
    }
    __syncthreads();

    const float M  = sM;
    const float iZ = 1.0f / sZ;

    // Context: 1024 elements, 4 per thread; split loop fully unrolled (MLP).
    {
        const float* pc = g_part_c + (size_t)b * SPLITS * DD;
#pragma unroll
        for (int k = 0; k < 4; k++) {
            const int d = k * NTHR + tid;
            float acc = 0.f;
#pragma unroll
            for (int j = 0; j < SPLITS; j++)
                acc += se[j] * pc[(size_t)j * DD + d];
            out[(size_t)b * DD + d] = acc * iZ;
        }
    }

    // Weights: 2048 elements, 8 per thread.
    {
        float* ow = out + (size_t)BB * DD + (size_t)b * TT;
        const float* sc = g_scores + b * TT;
#pragma unroll
        for (int k = 0; k < 8; k++) {
            const int i = k * NTHR + tid;
            ow[i] = __expf(sc[i] - M) * iZ;
        }
    }

    // Reset counter for next (graph-replayed) launch.
    if (tid == 0) g_count[b] = 0;
}

extern "C" void kernel_launch(void* const* d_in, const int* in_sizes, int n_in,
                              void* d_out, int out_size) {
    const float* q = (const float*)d_in[0];   // [32,1024]
    const float* v = (const float*)d_in[1];   // [32,2048,1024]
    float* out = (float*)d_out;               // context [32*1024] ++ weights [32*2048]

    dpa_fused<<<dim3(SPLITS, BB), NTHR>>>(q, v, out);
}

// round 5
// speedup vs baseline: 1.2149x; 1.2149x over previous
#include <cuda_runtime.h>
#include <math_constants.h>

// Problem dims (fixed by setup_inputs)
#define BB 32
#define TT 2048
#define DD 1024
#define SPLITS 32
#define TC (TT / SPLITS)      // 64 rows per block
#define RPI 4                 // rows per iteration
#define NTHR 256              // = DD/4 (one float4 lane per thread)

// Scratch (no cudaMalloc allowed)
__device__ float g_scores[BB * TT];
__device__ float g_part_m[BB * SPLITS];
__device__ float g_part_z[BB * SPLITS];
__device__ float g_part_c[(size_t)BB * SPLITS * DD];
__device__ unsigned int g_count[BB];   // zero-initialized; reset by consumer

// ---------------------------------------------------------------------------
// Single fused kernel with atomic fan-in. __launch_bounds__(256, 5) pins the
// register budget so the streaming path keeps 5 blocks/SM; the rare combine
// path may spill (L1-resident, executes for 32 of 1024 blocks only).
// ---------------------------------------------------------------------------
__global__ __launch_bounds__(NTHR, 5) void dpa_fused(const float* __restrict__ q,
                                                     const float* __restrict__ v,
                                                     float* __restrict__ out) {
    const int split = blockIdx.x;
    const int b     = blockIdx.y;
    const int tid   = threadIdx.x;
    const int lane  = tid & 31;
    const int warp  = tid >> 5;

    __shared__ float red[8][RPI];
    __shared__ float se[SPLITS];
    __shared__ float sM, sZ;
    __shared__ int   s_last;

    const float4 q4 = reinterpret_cast<const float4*>(q + (size_t)b * DD)[tid];

    float  m = -CUDART_INF_F;
    float  Z = 0.0f;
    float4 c = make_float4(0.f, 0.f, 0.f, 0.f);

    const int t0 = split * TC;
    const float4* vb = reinterpret_cast<const float4*>(v + (size_t)b * TT * DD) + tid;

    for (int it = 0; it < TC; it += RPI) {
        float4 vv[RPI];
        float  p[RPI];
#pragma unroll
        for (int r = 0; r < RPI; r++) {
            vv[r] = vb[(size_t)(t0 + it + r) * (DD / 4)];
            p[r]  = q4.x * vv[r].x + q4.y * vv[r].y + q4.z * vv[r].z + q4.w * vv[r].w;
        }
#pragma unroll
        for (int r = 0; r < RPI; r++) {
#pragma unroll
            for (int o = 16; o > 0; o >>= 1)
                p[r] += __shfl_xor_sync(0xffffffffu, p[r], o);
        }
        if (lane == 0) {
#pragma unroll
            for (int r = 0; r < RPI; r++) red[warp][r] = p[r];
        }
        __syncthreads();

        float s[RPI];
#pragma unroll
        for (int r = 0; r < RPI; r++) {
            float acc = 0.f;
#pragma unroll
            for (int w = 0; w < 8; w++) acc += red[w][r];
            s[r] = acc;
        }
        __syncthreads();  // before smem reuse next iter

        if (tid < RPI) g_scores[b * TT + t0 + it + tid] = s[tid];

        // Online softmax update (identical scalar math on all threads)
        float nm = m;
#pragma unroll
        for (int r = 0; r < RPI; r++) nm = fmaxf(nm, s[r]);
        const float f = __expf(m - nm);   // 0 on first iter (m = -inf)
        Z *= f;
        c.x *= f; c.y *= f; c.z *= f; c.w *= f;
#pragma unroll
        for (int r = 0; r < RPI; r++) {
            const float e = __expf(s[r] - nm);
            Z  += e;
            c.x += e * vv[r].x;
            c.y += e * vv[r].y;
            c.z += e * vv[r].z;
            c.w += e * vv[r].w;
        }
        m = nm;
    }

    // Publish per-split partials
    reinterpret_cast<float4*>(g_part_c + (size_t)(b * SPLITS + split) * DD)[tid] = c;
    if (tid == 0) {
        g_part_m[b * SPLITS + split] = m;
        g_part_z[b * SPLITS + split] = Z;
    }

    // Fan-in: last block for this batch performs the combine.
    __syncthreads();
    if (tid == 0) {
        __threadfence();
        const unsigned int old = atomicAdd(&g_count[b], 1u);
        s_last = (old == SPLITS - 1);
    }
    __syncthreads();
    if (!s_last) return;
    __threadfence();

    // ---- Combine stage (one block per batch, data is L2-resident) ----
    if (warp == 0) {
        const float mj = g_part_m[b * SPLITS + lane];   // SPLITS == 32
        float M = mj;
#pragma unroll
        for (int o = 16; o > 0; o >>= 1)
            M = fmaxf(M, __shfl_xor_sync(0xffffffffu, M, o));
        const float e = __expf(mj - M);
        se[lane] = e;
        float z = g_part_z[b * SPLITS + lane] * e;
#pragma unroll
        for (int o = 16; o > 0; o >>= 1)
            z += __shfl_xor_sync(0xffffffffu, z, o);
        if (lane == 0) { sM = M; sZ = z; }
    }
    __syncthreads();

    const float M  = sM;
    const float iZ = 1.0f / sZ;

    // Context: 1024 elements, 4 per thread; bounded unroll keeps regs small.
    {
        const float* pc = g_part_c + (size_t)b * SPLITS * DD;
        for (int k = 0; k < 4; k++) {
            const int d = k * NTHR + tid;
            float acc = 0.f;
#pragma unroll 8
            for (int j = 0; j < SPLITS; j++)
                acc += se[j] * pc[(size_t)j * DD + d];
            out[(size_t)b * DD + d] = acc * iZ;
        }
    }

    // Weights: 2048 elements, 8 per thread.
    {
        float* ow = out + (size_t)BB * DD + (size_t)b * TT;
        const float* sc = g_scores + b * TT;
#pragma unroll 4
        for (int k = 0; k < 8; k++) {
            const int i = k * NTHR + tid;
            ow[i] = __expf(sc[i] - M) * iZ;
        }
    }

    // Reset counter for next (graph-replayed) launch.
    if (tid == 0) g_count[b] = 0;
}

extern "C" void kernel_launch(void* const* d_in, const int* in_sizes, int n_in,
                              void* d_out, int out_size) {
    const float* q = (const float*)d_in[0];   // [32,1024]
    const float* v = (const float*)d_in[1];   // [32,2048,1024]
    float* out = (float*)d_out;               // context [32*1024] ++ weights [32*2048]

    dpa_fused<<<dim3(SPLITS, BB), NTHR>>>(q, v, out);
}

// round 6
// speedup vs baseline: 1.4420x; 1.1869x over previous
#include <cuda_runtime.h>
#include <math_constants.h>

// Problem dims (fixed by setup_inputs)
#define BB 32
#define TT 2048
#define DD 1024
#define SPLITS 64
#define TC (TT / SPLITS)      // 32 rows per block (R1-proven streaming shape)
#define RPI 4                 // rows per iteration
#define NTHR 256              // = DD/4 (one float4 lane per thread)

// Scratch (no cudaMalloc allowed)
__device__ float g_scores[BB * TT];
__device__ float g_part_m[BB * SPLITS];
__device__ float g_part_z[BB * SPLITS];
__device__ float g_part_c[(size_t)BB * SPLITS * DD];
__device__ unsigned int g_count[BB];   // zero-initialized; reset by consumer

// ---------------------------------------------------------------------------
// Single fused kernel with atomic fan-in. Streaming path identical to the
// R1 pass1 (46us, 75.8% DRAM). The LAST block per batch performs that
// batch's combine with fully vectorized (float4) L2/DRAM reads.
// ---------------------------------------------------------------------------
__global__ __launch_bounds__(NTHR, 5) void dpa_fused(const float* __restrict__ q,
                                                     const float* __restrict__ v,
                                                     float* __restrict__ out) {
    const int split = blockIdx.x;
    const int b     = blockIdx.y;
    const int tid   = threadIdx.x;
    const int lane  = tid & 31;
    const int warp  = tid >> 5;

    __shared__ float red[8][RPI];
    __shared__ float se[SPLITS];
    __shared__ float sM, sZ;
    __shared__ int   s_last;

    const float4 q4 = reinterpret_cast<const float4*>(q + (size_t)b * DD)[tid];

    float  m = -CUDART_INF_F;
    float  Z = 0.0f;
    float4 c = make_float4(0.f, 0.f, 0.f, 0.f);

    const int t0 = split * TC;
    const float4* vb = reinterpret_cast<const float4*>(v + (size_t)b * TT * DD) + tid;

    for (int it = 0; it < TC; it += RPI) {
        float4 vv[RPI];
        float  p[RPI];
#pragma unroll
        for (int r = 0; r < RPI; r++) {
            vv[r] = vb[(size_t)(t0 + it + r) * (DD / 4)];
            p[r]  = q4.x * vv[r].x + q4.y * vv[r].y + q4.z * vv[r].z + q4.w * vv[r].w;
        }
#pragma unroll
        for (int r = 0; r < RPI; r++) {
#pragma unroll
            for (int o = 16; o > 0; o >>= 1)
                p[r] += __shfl_xor_sync(0xffffffffu, p[r], o);
        }
        if (lane == 0) {
#pragma unroll
            for (int r = 0; r < RPI; r++) red[warp][r] = p[r];
        }
        __syncthreads();

        float s[RPI];
#pragma unroll
        for (int r = 0; r < RPI; r++) {
            float acc = 0.f;
#pragma unroll
            for (int w = 0; w < 8; w++) acc += red[w][r];
            s[r] = acc;
        }
        __syncthreads();  // before smem reuse next iter

        if (tid < RPI) g_scores[b * TT + t0 + it + tid] = s[tid];

        // Online softmax update (identical scalar math on all threads)
        float nm = m;
#pragma unroll
        for (int r = 0; r < RPI; r++) nm = fmaxf(nm, s[r]);
        const float f = __expf(m - nm);   // 0 on first iter (m = -inf)
        Z *= f;
        c.x *= f; c.y *= f; c.z *= f; c.w *= f;
#pragma unroll
        for (int r = 0; r < RPI; r++) {
            const float e = __expf(s[r] - nm);
            Z  += e;
            c.x += e * vv[r].x;
            c.y += e * vv[r].y;
            c.z += e * vv[r].z;
            c.w += e * vv[r].w;
        }
        m = nm;
    }

    // Publish per-split partials
    reinterpret_cast<float4*>(g_part_c + (size_t)(b * SPLITS + split) * DD)[tid] = c;
    if (tid == 0) {
        g_part_m[b * SPLITS + split] = m;
        g_part_z[b * SPLITS + split] = Z;
    }

    // Fan-in: last block for this batch performs the combine.
    __syncthreads();
    if (tid == 0) {
        __threadfence();
        const unsigned int old = atomicAdd(&g_count[b], 1u);
        s_last = (old == SPLITS - 1);
    }
    __syncthreads();
    if (!s_last) return;
    __threadfence();

    // ---- Combine stage (one block per batch) ----
    // M, Z over 64 splits: warp 0, two elements per lane.
    if (warp == 0) {
        const float m0 = g_part_m[b * SPLITS + lane];
        const float m1 = g_part_m[b * SPLITS + lane + 32];
        float M = fmaxf(m0, m1);
#pragma unroll
        for (int o = 16; o > 0; o >>= 1)
            M = fmaxf(M, __shfl_xor_sync(0xffffffffu, M, o));
        const float e0 = __expf(m0 - M);
        const float e1 = __expf(m1 - M);
        se[lane]      = e0;
        se[lane + 32] = e1;
        float z = g_part_z[b * SPLITS + lane] * e0 +
                  g_part_z[b * SPLITS + lane + 32] * e1;
#pragma unroll
        for (int o = 16; o > 0; o >>= 1)
            z += __shfl_xor_sync(0xffffffffu, z, o);
        if (lane == 0) { sM = M; sZ = z; }
    }
    __syncthreads();

    const float M  = sM;
    const float iZ = 1.0f / sZ;

    // Context: one float4 output per thread; 64 vectorized partial loads.
    {
        const float4* pc = reinterpret_cast<const float4*>(
                               g_part_c + (size_t)b * SPLITS * DD) + tid;
        float4 a = make_float4(0.f, 0.f, 0.f, 0.f);
#pragma unroll 16
        for (int j = 0; j < SPLITS; j++) {
            const float4 p4 = pc[(size_t)j * (DD / 4)];
            const float  e  = se[j];
            a.x += e * p4.x; a.y += e * p4.y; a.z += e * p4.z; a.w += e * p4.w;
        }
        float4 o;
        o.x = a.x * iZ; o.y = a.y * iZ; o.z = a.z * iZ; o.w = a.w * iZ;
        reinterpret_cast<float4*>(out + (size_t)b * DD)[tid] = o;
    }

    // Weights: 2048 floats per batch -> 2 float4 per thread.
    {
        const float4* sc = reinterpret_cast<const float4*>(g_scores + b * TT);
        float4* ow = reinterpret_cast<float4*>(out + (size_t)BB * DD + (size_t)b * TT);
#pragma unroll
        for (int k = 0; k < 2; k++) {
            const float4 s4 = sc[k * NTHR + tid];
            float4 w;
            w.x = __expf(s4.x - M) * iZ;
            w.y = __expf(s4.y - M) * iZ;
            w.z = __expf(s4.z - M) * iZ;
            w.w = __expf(s4.w - M) * iZ;
            ow[k * NTHR + tid] = w;
        }
    }

    // Reset counter for next (graph-replayed) launch.
    if (tid == 0) g_count[b] = 0;
}

extern "C" void kernel_launch(void* const* d_in, const int* in_sizes, int n_in,
                              void* d_out, int out_size) {
    const float* q = (const float*)d_in[0];   // [32,1024]
    const float* v = (const float*)d_in[1];   // [32,2048,1024]
    float* out = (float*)d_out;               // context [32*1024] ++ weights [32*2048]

    dpa_fused<<<dim3(SPLITS, BB), NTHR>>>(q, v, out);
}